// round 2
// baseline (speedup 1.0000x reference)
#include <cuda_runtime.h>
#include <cuda_bf16.h>

#define N_NODES  100000
#define N_EDGES  1600000
#define N_GRAPHS 64
#define HID      64
#define LN_EPS   1e-5f
#define FULL     0xffffffffu

// -------- persistent device scratch --------
__device__ int    g_deg[N_NODES];
__device__ int    g_rowptr[N_NODES];
__device__ int    g_cursor[N_NODES];
__device__ int    g_ssrc[N_EDGES];     // src indices grouped by dst
__device__ float  g_adotl[N_NODES];    // att . (x[n] @ W_l)   (no bias)
__device__ double g_S[N_GRAPHS];
__device__ int    g_cnt[N_GRAPHS];
__device__ double g_sum, g_sq;

// -------- kernel 0: zero --------
__global__ void k_zero() {
    int i = blockIdx.x * blockDim.x + threadIdx.x;
    int stride = gridDim.x * blockDim.x;
    for (int t = i; t < N_NODES; t += stride) g_deg[t] = 0;
    if (i < N_GRAPHS) { g_S[i] = 0.0; g_cnt[i] = 0; }
    if (i == 0) { g_sum = 0.0; g_sq = 0.0; }
}

// -------- kernel 1: in-degree histogram --------
__global__ void k_hist(const int* __restrict__ ei) {
    int e = blockIdx.x * blockDim.x + threadIdx.x;
    if (e < N_EDGES) atomicAdd(&g_deg[ei[N_EDGES + e]], 1);
}

// -------- kernel 2: per-node att.(x@W_l), warp = 2 nodes --------
__global__ void k_pre(const float* __restrict__ x, const float* __restrict__ W_l,
                      const float* __restrict__ att) {
    int gtid = blockIdx.x * blockDim.x + threadIdx.x;
    int lane = threadIdx.x & 31, half = lane >> 4, j = lane & 15;
    int n = (gtid >> 5) * 2 + half;
    const float4* x4  = (const float4*)x;
    const float4* wl4 = (const float4*)W_l;
    float4 w0 = wl4[j], w1 = wl4[16 + j], w2 = wl4[32 + j], w3 = wl4[48 + j];
    float4 av = ((const float4*)att)[j];
    float4 xn = x4[n];
    float ax = xn.x * w0.x + xn.y * w1.x + xn.z * w2.x + xn.w * w3.x;
    float ay = xn.x * w0.y + xn.y * w1.y + xn.z * w2.y + xn.w * w3.y;
    float az = xn.x * w0.z + xn.y * w1.z + xn.z * w2.z + xn.w * w3.z;
    float aw = xn.x * w0.w + xn.y * w1.w + xn.z * w2.w + xn.w * w3.w;
    float p = av.x * ax + av.y * ay + av.z * az + av.w * aw;
    p += __shfl_xor_sync(FULL, p, 8);
    p += __shfl_xor_sync(FULL, p, 4);
    p += __shfl_xor_sync(FULL, p, 2);
    p += __shfl_xor_sync(FULL, p, 1);
    if (j == 0) g_adotl[n] = p;
}

// -------- kernel 3: exclusive scan of degrees (single block) --------
__global__ void k_scan() {
    __shared__ int sh[1024];
    const int T = 1024;
    int t = threadIdx.x;
    const int per = (N_NODES + T - 1) / T;   // 98
    int beg = t * per;
    int end = min(beg + per, N_NODES);
    int sum = 0;
    for (int i = beg; i < end; i++) sum += g_deg[i];
    sh[t] = sum;
    __syncthreads();
    for (int off = 1; off < T; off <<= 1) {
        int v = (t >= off) ? sh[t - off] : 0;
        __syncthreads();
        sh[t] += v;
        __syncthreads();
    }
    int run = (t == 0) ? 0 : sh[t - 1];
    for (int i = beg; i < end; i++) {
        g_rowptr[i] = run;
        g_cursor[i] = run;
        run += g_deg[i];
    }
}

// -------- kernel 4: scatter src indices into dst-grouped order --------
__global__ void k_scatter(const int* __restrict__ ei) {
    int e = blockIdx.x * blockDim.x + threadIdx.x;
    if (e >= N_EDGES) return;
    int src = ei[e];
    int dst = ei[N_EDGES + e];
    int pos = atomicAdd(&g_cursor[dst], 1);
    g_ssrc[pos] = src;
}

// -------- kernel 5: fused GATv2 aggregate + finalize + LN/pool stats --------
// warp per node; within warp: 2 edges per iteration, 16 lanes per edge,
// lane j owns channels [4j, 4j+4).
__global__ void k_gat(const float* __restrict__ x,
                      const float* __restrict__ W_l, const float* __restrict__ b_l,
                      const float* __restrict__ W_r, const float* __restrict__ b_r,
                      const float* __restrict__ att,
                      const float* __restrict__ conv_bias,
                      const float* __restrict__ ln_w, const float* __restrict__ lin_w,
                      const int* __restrict__ batch) {
    __shared__ float sS[N_GRAPHS];
    __shared__ int   sC[N_GRAPHS];
    __shared__ float sSum, sSq;
    int tid = threadIdx.x;
    if (tid < N_GRAPHS) { sS[tid] = 0.f; sC[tid] = 0; }
    if (tid == 0) { sSum = 0.f; sSq = 0.f; }
    __syncthreads();

    int n    = (blockIdx.x * blockDim.x + tid) >> 5;
    int lane = tid & 31;
    int half = lane >> 4;
    int j    = lane & 15;

    const float4* x4  = (const float4*)x;
    const float4* wl4 = (const float4*)W_l;
    const float4* wr4 = (const float4*)W_r;

    float4 wl0 = wl4[j], wl1 = wl4[16 + j], wl2 = wl4[32 + j], wl3 = wl4[48 + j];
    float4 av  = ((const float4*)att)[j];

    // node-side: xrb = x[n]@W_r + b_r + b_l  (b_l folded so h = a + xrb)
    float4 xn  = x4[n];
    float4 wr0 = wr4[j], wr1 = wr4[16 + j], wr2 = wr4[32 + j], wr3 = wr4[48 + j];
    float4 bl4 = ((const float4*)b_l)[j];
    float4 br4 = ((const float4*)b_r)[j];
    float4 xrb;
    xrb.x = bl4.x + br4.x + xn.x * wr0.x + xn.y * wr1.x + xn.z * wr2.x + xn.w * wr3.x;
    xrb.y = bl4.y + br4.y + xn.x * wr0.y + xn.y * wr1.y + xn.z * wr2.y + xn.w * wr3.y;
    xrb.z = bl4.z + br4.z + xn.x * wr0.z + xn.y * wr1.z + xn.z * wr2.z + xn.w * wr3.z;
    xrb.w = bl4.w + br4.w + xn.x * wr0.w + xn.y * wr1.w + xn.z * wr2.w + xn.w * wr3.w;
    // node scalar: att . xrb
    float ad = av.x * xrb.x + av.y * xrb.y + av.z * xrb.z + av.w * xrb.w;
    ad += __shfl_xor_sync(FULL, ad, 8);
    ad += __shfl_xor_sync(FULL, ad, 4);
    ad += __shfl_xor_sync(FULL, ad, 2);
    ad += __shfl_xor_sync(FULL, ad, 1);

    int start = g_rowptr[n];
    int cnt   = g_deg[n];

    float4 acc = make_float4(0.f, 0.f, 0.f, 0.f);
    float  den = 0.f;

    for (int base = 0; base < cnt; base += 32) {
        int idx = base + lane;
        int s_i = (idx < cnt) ? g_ssrc[start + idx] : 0;
        int m = min(32, cnt - base);
        for (int e2 = 0; e2 < m; e2 += 2) {
            int eidx  = e2 + half;
            int src   = __shfl_sync(FULL, s_i, eidx);
            bool valid = eidx < m;

            float4 xs  = x4[src];                 // 16B broadcast load (L2-resident)
            float  adl = g_adotl[src];            // scalar broadcast load

            // a = x[src] @ W_l  (no bias)
            float ax = xs.x * wl0.x + xs.y * wl1.x + xs.z * wl2.x + xs.w * wl3.x;
            float ay = xs.x * wl0.y + xs.y * wl1.y + xs.z * wl2.y + xs.w * wl3.y;
            float az = xs.x * wl0.z + xs.y * wl1.z + xs.z * wl2.z + xs.w * wl3.z;
            float aw = xs.x * wl0.w + xs.y * wl1.w + xs.z * wl2.w + xs.w * wl3.w;

            float h0 = ax + xrb.x, h1 = ay + xrb.y, h2 = az + xrb.z, h3 = aw + xrb.w;
            // 0.4 * sum att * |h|   (linear part handled via adl + ad)
            float eabs = av.x * fabsf(h0);
            eabs = fmaf(av.y, fabsf(h1), eabs);
            eabs = fmaf(av.z, fabsf(h2), eabs);
            eabs = fmaf(av.w, fabsf(h3), eabs);
            eabs += __shfl_xor_sync(FULL, eabs, 8);
            eabs += __shfl_xor_sync(FULL, eabs, 4);
            eabs += __shfl_xor_sync(FULL, eabs, 2);
            eabs += __shfl_xor_sync(FULL, eabs, 1);

            float e  = 0.6f * (adl + ad) + 0.4f * eabs;
            float ex = valid ? __expf(e) : 0.f;   // softmax shift algebraically cancels

            den   += ex;
            acc.x = fmaf(ex, ax, acc.x);
            acc.y = fmaf(ex, ay, acc.y);
            acc.z = fmaf(ex, az, acc.z);
            acc.w = fmaf(ex, aw, acc.w);
        }
    }

    // combine the two halves
    den   += __shfl_xor_sync(FULL, den, 16);
    acc.x += __shfl_xor_sync(FULL, acc.x, 16);
    acc.y += __shfl_xor_sync(FULL, acc.y, 16);
    acc.z += __shfl_xor_sync(FULL, acc.z, 16);
    acc.w += __shfl_xor_sync(FULL, acc.w, 16);

    float invd = den > 0.f ? 1.f / den : 0.f;
    float bsel = den > 0.f ? 1.f : 0.f;          // b_l only applies if node has edges
    float4 cb = ((const float4*)conv_bias)[j];
    float4 v;
    v.x = fmaxf(fmaf(acc.x, invd, fmaf(bsel, bl4.x, cb.x)), 0.f);
    v.y = fmaxf(fmaf(acc.y, invd, fmaf(bsel, bl4.y, cb.y)), 0.f);
    v.z = fmaxf(fmaf(acc.z, invd, fmaf(bsel, bl4.z, cb.z)), 0.f);
    v.w = fmaxf(fmaf(acc.w, invd, fmaf(bsel, bl4.w, cb.w)), 0.f);

    float4 lw = ((const float4*)ln_w)[j];
    float4 pw = ((const float4*)lin_w)[j];
    float s = v.x + v.y + v.z + v.w;
    float q = v.x * v.x + v.y * v.y + v.z * v.z + v.w * v.w;
    float t = v.x * lw.x * pw.x + v.y * lw.y * pw.y + v.z * lw.z * pw.z + v.w * lw.w * pw.w;
    #pragma unroll
    for (int off = 8; off > 0; off >>= 1) {
        s += __shfl_xor_sync(FULL, s, off);
        q += __shfl_xor_sync(FULL, q, off);
        t += __shfl_xor_sync(FULL, t, off);
    }

    if (lane == 0) {
        int g = batch[n];
        atomicAdd(&sS[g], t);
        atomicAdd(&sC[g], 1);
        atomicAdd(&sSum, s);
        atomicAdd(&sSq,  q);
    }
    __syncthreads();

    if (tid < N_GRAPHS && sC[tid] != 0) {
        atomicAdd(&g_S[tid], (double)sS[tid]);
        atomicAdd(&g_cnt[tid], sC[tid]);
    }
    if (tid == 0) {
        atomicAdd(&g_sum, (double)sSum);
        atomicAdd(&g_sq,  (double)sSq);
    }
}

// -------- kernel 6: final scalar combine + sigmoid --------
__global__ void k_final(const float* __restrict__ ln_w, const float* __restrict__ ln_b,
                        const float* __restrict__ lin_w, const float* __restrict__ lin_b,
                        float* __restrict__ out) {
    __shared__ float sW, sB;
    int t = threadIdx.x;
    if (t == 0) {
        float W = 0.f, B = 0.f;
        for (int i = 0; i < HID; i++) {
            W += ln_w[i] * lin_w[i];
            B += ln_b[i] * lin_w[i];
        }
        sW = W;
        sB = B + lin_b[0];
    }
    __syncthreads();

    double Ntot = (double)N_NODES * HID;
    double mu_d  = g_sum / Ntot;
    double var_d = g_sq / Ntot - mu_d * mu_d;
    float mu  = (float)mu_d;
    float inv = rsqrtf((float)var_d + LN_EPS);

    float cnt = fmaxf((float)g_cnt[t], 1.f);
    float y = inv * ((float)g_S[t] / cnt - mu * sW) + sB;
    out[t] = 1.f / (1.f + __expf(-y));
}

extern "C" void kernel_launch(void* const* d_in, const int* in_sizes, int n_in,
                              void* d_out, int out_size) {
    const float* x         = (const float*)d_in[0];
    const int*   ei        = (const int*)  d_in[1];
    const int*   batch     = (const int*)  d_in[2];
    const float* W_l       = (const float*)d_in[3];
    const float* b_l       = (const float*)d_in[4];
    const float* W_r       = (const float*)d_in[5];
    const float* b_r       = (const float*)d_in[6];
    const float* att       = (const float*)d_in[7];
    const float* conv_bias = (const float*)d_in[8];
    const float* ln_w      = (const float*)d_in[9];
    const float* ln_b      = (const float*)d_in[10];
    const float* lin_w     = (const float*)d_in[11];
    const float* lin_b     = (const float*)d_in[12];
    float* out = (float*)d_out;

    k_zero<<<256, 256>>>();
    k_hist<<<N_EDGES / 256, 256>>>(ei);
    k_pre<<<N_NODES / 16, 256>>>(x, W_l, att);
    k_scan<<<1, 1024>>>();
    k_scatter<<<N_EDGES / 256, 256>>>(ei);
    k_gat<<<N_NODES / 8, 256>>>(x, W_l, b_l, W_r, b_r, att, conv_bias, ln_w, lin_w, batch);
    k_final<<<1, N_GRAPHS>>>(ln_w, ln_b, lin_w, lin_b, out);
}

// round 3
// speedup vs baseline: 1.6631x; 1.6631x over previous
#include <cuda_runtime.h>
#include <cuda_bf16.h>

#define N_NODES  100000
#define N_EDGES  1600000
#define N_GRAPHS 64
#define HID      64
#define LN_EPS   1e-5f
#define FULL     0xffffffffu

#define SCAN_BLOCKS 400
#define SCAN_CHUNK  250     // 400 * 250 = 100000 exactly
#define GAT_BLOCKS  1184    // 8 * 148

// -------- persistent device scratch --------
__device__ int    g_deg[N_NODES];
__device__ int    g_rowptr[N_NODES];
__device__ int    g_cursor[N_NODES];
__device__ int    g_ssrc[N_EDGES];       // src indices grouped by dst
__device__ int    g_bsum[SCAN_BLOCKS];
__device__ int    g_boff[SCAN_BLOCKS];
__device__ double g_S[N_GRAPHS];
__device__ int    g_cnt[N_GRAPHS];
__device__ double g_sum, g_sq;

// -------- kernel 0: zero --------
__global__ void k_zero() {
    int i = blockIdx.x * blockDim.x + threadIdx.x;
    int stride = gridDim.x * blockDim.x;
    for (int t = i; t < N_NODES; t += stride) g_deg[t] = 0;
    if (i < N_GRAPHS) { g_S[i] = 0.0; g_cnt[i] = 0; }
    if (i == 0) { g_sum = 0.0; g_sq = 0.0; }
}

// -------- kernel 1: in-degree histogram --------
__global__ void k_hist(const int* __restrict__ ei) {
    int e = blockIdx.x * blockDim.x + threadIdx.x;
    if (e < N_EDGES) atomicAdd(&g_deg[ei[N_EDGES + e]], 1);
}

// -------- scan stage 1: per-block local exclusive scan + block total --------
__global__ void k_scan1() {
    __shared__ int sh[256];
    int t = threadIdx.x;
    int base = blockIdx.x * SCAN_CHUNK;
    int d = (t < SCAN_CHUNK) ? g_deg[base + t] : 0;
    sh[t] = d;
    __syncthreads();
    #pragma unroll
    for (int off = 1; off < 256; off <<= 1) {
        int v = (t >= off) ? sh[t - off] : 0;
        __syncthreads();
        sh[t] += v;
        __syncthreads();
    }
    if (t < SCAN_CHUNK) g_rowptr[base + t] = sh[t] - d;   // local exclusive
    if (t == 255) g_bsum[blockIdx.x] = sh[255];
}

// -------- scan stage 2: scan the 400 block sums (single tiny block) --------
__global__ void k_scan2() {
    __shared__ int sh[512];
    int t = threadIdx.x;
    int d = (t < SCAN_BLOCKS) ? g_bsum[t] : 0;
    sh[t] = d;
    __syncthreads();
    #pragma unroll
    for (int off = 1; off < 512; off <<= 1) {
        int v = (t >= off) ? sh[t - off] : 0;
        __syncthreads();
        sh[t] += v;
        __syncthreads();
    }
    if (t < SCAN_BLOCKS) g_boff[t] = sh[t] - d;           // exclusive
}

// -------- scan stage 3: add block offsets, produce rowptr + cursor --------
__global__ void k_scan3() {
    int t = threadIdx.x;
    int base = blockIdx.x * SCAN_CHUNK;
    if (t < SCAN_CHUNK) {
        int v = g_rowptr[base + t] + g_boff[blockIdx.x];
        g_rowptr[base + t] = v;
        g_cursor[base + t] = v;
    }
}

// -------- kernel 4: scatter src indices into dst-grouped order --------
__global__ void k_scatter(const int* __restrict__ ei) {
    int e = blockIdx.x * blockDim.x + threadIdx.x;
    if (e >= N_EDGES) return;
    int src = ei[e];
    int dst = ei[N_EDGES + e];
    int pos = atomicAdd(&g_cursor[dst], 1);
    g_ssrc[pos] = src;
}

// -------- kernel 5: fused GATv2 aggregate + finalize + LN/pool stats --------
// grid-stride warp-per-node; within warp: 2 edges/iter, 16 lanes/edge,
// lane j owns channels [4j, 4j+4).
__global__ void __launch_bounds__(256)
k_gat(const float* __restrict__ x,
      const float* __restrict__ W_l, const float* __restrict__ b_l,
      const float* __restrict__ W_r, const float* __restrict__ b_r,
      const float* __restrict__ att,
      const float* __restrict__ conv_bias,
      const float* __restrict__ ln_w, const float* __restrict__ lin_w,
      const int* __restrict__ batch) {
    __shared__ float sS[N_GRAPHS];
    __shared__ int   sC[N_GRAPHS];
    __shared__ float sSum, sSq;
    int tid = threadIdx.x;
    if (tid < N_GRAPHS) { sS[tid] = 0.f; sC[tid] = 0; }
    if (tid == 0) { sSum = 0.f; sSq = 0.f; }
    __syncthreads();

    int lane = tid & 31;
    int half = lane >> 4;
    int j    = lane & 15;
    int warpId = (blockIdx.x * blockDim.x + tid) >> 5;
    const int nWarps = (GAT_BLOCKS * 256) >> 5;

    const float4* x4  = (const float4*)x;
    const float4* wl4 = (const float4*)W_l;
    const float4* wr4 = (const float4*)W_r;

    float4 wl0 = wl4[j], wl1 = wl4[16 + j], wl2 = wl4[32 + j], wl3 = wl4[48 + j];
    float4 wr0 = wr4[j], wr1 = wr4[16 + j], wr2 = wr4[32 + j], wr3 = wr4[48 + j];
    float4 av  = ((const float4*)att)[j];
    float4 bl4 = ((const float4*)b_l)[j];
    float4 br4 = ((const float4*)b_r)[j];
    float4 cb  = ((const float4*)conv_bias)[j];
    float4 lw  = ((const float4*)ln_w)[j];
    float4 pw  = ((const float4*)lin_w)[j];

    // wa_l[k] = sum_c W_l[k][c]*att[c]; wa_r likewise; cad = att.(b_l+b_r)
    float4 wal, war;
    float cad;
    {
        float p0 = wl0.x*av.x + wl0.y*av.y + wl0.z*av.z + wl0.w*av.w;
        float p1 = wl1.x*av.x + wl1.y*av.y + wl1.z*av.z + wl1.w*av.w;
        float p2 = wl2.x*av.x + wl2.y*av.y + wl2.z*av.z + wl2.w*av.w;
        float p3 = wl3.x*av.x + wl3.y*av.y + wl3.z*av.z + wl3.w*av.w;
        float r0 = wr0.x*av.x + wr0.y*av.y + wr0.z*av.z + wr0.w*av.w;
        float r1 = wr1.x*av.x + wr1.y*av.y + wr1.z*av.z + wr1.w*av.w;
        float r2 = wr2.x*av.x + wr2.y*av.y + wr2.z*av.z + wr2.w*av.w;
        float r3 = wr3.x*av.x + wr3.y*av.y + wr3.z*av.z + wr3.w*av.w;
        float bb = (bl4.x+br4.x)*av.x + (bl4.y+br4.y)*av.y
                 + (bl4.z+br4.z)*av.z + (bl4.w+br4.w)*av.w;
        #pragma unroll
        for (int off = 8; off > 0; off >>= 1) {
            p0 += __shfl_xor_sync(FULL, p0, off);
            p1 += __shfl_xor_sync(FULL, p1, off);
            p2 += __shfl_xor_sync(FULL, p2, off);
            p3 += __shfl_xor_sync(FULL, p3, off);
            r0 += __shfl_xor_sync(FULL, r0, off);
            r1 += __shfl_xor_sync(FULL, r1, off);
            r2 += __shfl_xor_sync(FULL, r2, off);
            r3 += __shfl_xor_sync(FULL, r3, off);
            bb += __shfl_xor_sync(FULL, bb, off);
        }
        wal = make_float4(p0, p1, p2, p3);
        war = make_float4(r0, r1, r2, r3);
        cad = bb;
    }

    float regS = 0.f, regQ = 0.f;   // per-warp LN partials across its nodes

    for (int n = warpId; n < N_NODES; n += nWarps) {
        float4 xn = x4[n];
        // xrb = x[n]@W_r + b_r + b_l  (b_l folded so h = xl_src + xrb)
        float4 xrb;
        xrb.x = bl4.x + br4.x + xn.x*wr0.x + xn.y*wr1.x + xn.z*wr2.x + xn.w*wr3.x;
        xrb.y = bl4.y + br4.y + xn.x*wr0.y + xn.y*wr1.y + xn.z*wr2.y + xn.w*wr3.y;
        xrb.z = bl4.z + br4.z + xn.x*wr0.z + xn.y*wr1.z + xn.z*wr2.z + xn.w*wr3.z;
        xrb.w = bl4.w + br4.w + xn.x*wr0.w + xn.y*wr1.w + xn.z*wr2.w + xn.w*wr3.w;
        // ad = att . xrb = x[n].war + cad  (exact: linear)
        float ad = xn.x*war.x + xn.y*war.y + xn.z*war.z + xn.w*war.w + cad;

        int start = g_rowptr[n];
        int cnt   = g_deg[n];

        float4 acc = make_float4(0.f, 0.f, 0.f, 0.f);  // sum ex * x[src] (4-dim!)
        float  den = 0.f;

        for (int base = 0; base < cnt; base += 32) {
            int idx = base + lane;
            int s_i = (idx < cnt) ? g_ssrc[start + idx] : 0;
            int m = min(32, cnt - base);
            for (int e2 = 0; e2 < m; e2 += 2) {
                int eidx = e2 + half;
                int src  = __shfl_sync(FULL, s_i, eidx);
                bool valid = eidx < m;

                float4 xs = x4[src];                 // only gather (16B, L2-resident)

                // adl = att.(x[src]@W_l) = x[src].wal  (exact linear part)
                float adl = xs.x*wal.x + xs.y*wal.y + xs.z*wal.z + xs.w*wal.w;

                // a = x[src]@W_l (this lane's 4-channel slice), for |h| only
                float ax = xs.x*wl0.x + xs.y*wl1.x + xs.z*wl2.x + xs.w*wl3.x;
                float ay = xs.x*wl0.y + xs.y*wl1.y + xs.z*wl2.y + xs.w*wl3.y;
                float az = xs.x*wl0.z + xs.y*wl1.z + xs.z*wl2.z + xs.w*wl3.z;
                float aw = xs.x*wl0.w + xs.y*wl1.w + xs.z*wl2.w + xs.w*wl3.w;

                float eabs = av.x * fabsf(ax + xrb.x);
                eabs = fmaf(av.y, fabsf(ay + xrb.y), eabs);
                eabs = fmaf(av.z, fabsf(az + xrb.z), eabs);
                eabs = fmaf(av.w, fabsf(aw + xrb.w), eabs);
                eabs += __shfl_xor_sync(FULL, eabs, 8);
                eabs += __shfl_xor_sync(FULL, eabs, 4);
                eabs += __shfl_xor_sync(FULL, eabs, 2);
                eabs += __shfl_xor_sync(FULL, eabs, 1);

                float e  = 0.6f * (adl + ad) + 0.4f * eabs;
                float ex = valid ? __expf(e) : 0.f;   // softmax shift cancels exactly

                den  += ex;
                acc.x = fmaf(ex, xs.x, acc.x);
                acc.y = fmaf(ex, xs.y, acc.y);
                acc.z = fmaf(ex, xs.z, acc.z);
                acc.w = fmaf(ex, xs.w, acc.w);
            }
        }

        // combine the two 16-lane halves
        den   += __shfl_xor_sync(FULL, den, 16);
        acc.x += __shfl_xor_sync(FULL, acc.x, 16);
        acc.y += __shfl_xor_sync(FULL, acc.y, 16);
        acc.z += __shfl_xor_sync(FULL, acc.z, 16);
        acc.w += __shfl_xor_sync(FULL, acc.w, 16);

        // out = (acc @ W_l)/den + b_l + conv_bias, relu
        float ox = acc.x*wl0.x + acc.y*wl1.x + acc.z*wl2.x + acc.w*wl3.x;
        float oy = acc.x*wl0.y + acc.y*wl1.y + acc.z*wl2.y + acc.w*wl3.y;
        float oz = acc.x*wl0.z + acc.y*wl1.z + acc.z*wl2.z + acc.w*wl3.z;
        float ow = acc.x*wl0.w + acc.y*wl1.w + acc.z*wl2.w + acc.w*wl3.w;

        float invd = den > 0.f ? 1.f / den : 0.f;
        float bsel = den > 0.f ? 1.f : 0.f;
        float4 v;
        v.x = fmaxf(fmaf(ox, invd, fmaf(bsel, bl4.x, cb.x)), 0.f);
        v.y = fmaxf(fmaf(oy, invd, fmaf(bsel, bl4.y, cb.y)), 0.f);
        v.z = fmaxf(fmaf(oz, invd, fmaf(bsel, bl4.z, cb.z)), 0.f);
        v.w = fmaxf(fmaf(ow, invd, fmaf(bsel, bl4.w, cb.w)), 0.f);

        float s = v.x + v.y + v.z + v.w;
        float q = v.x*v.x + v.y*v.y + v.z*v.z + v.w*v.w;
        float t = v.x*lw.x*pw.x + v.y*lw.y*pw.y + v.z*lw.z*pw.z + v.w*lw.w*pw.w;
        #pragma unroll
        for (int off = 8; off > 0; off >>= 1) {
            s += __shfl_xor_sync(FULL, s, off);
            q += __shfl_xor_sync(FULL, q, off);
            t += __shfl_xor_sync(FULL, t, off);
        }
        if (lane == 0) {
            int g = batch[n];
            atomicAdd(&sS[g], t);
            atomicAdd(&sC[g], 1);
            regS += s;
            regQ += q;
        }
    }

    if (lane == 0) {
        atomicAdd(&sSum, regS);
        atomicAdd(&sSq,  regQ);
    }
    __syncthreads();

    if (tid < N_GRAPHS && sC[tid] != 0) {
        atomicAdd(&g_S[tid], (double)sS[tid]);
        atomicAdd(&g_cnt[tid], sC[tid]);
    }
    if (tid == 0) {
        atomicAdd(&g_sum, (double)sSum);
        atomicAdd(&g_sq,  (double)sSq);
    }
}

// -------- kernel 6: final scalar combine + sigmoid --------
__global__ void k_final(const float* __restrict__ ln_w, const float* __restrict__ ln_b,
                        const float* __restrict__ lin_w, const float* __restrict__ lin_b,
                        float* __restrict__ out) {
    __shared__ float sW, sB;
    int t = threadIdx.x;
    if (t == 0) {
        float W = 0.f, B = 0.f;
        for (int i = 0; i < HID; i++) {
            W += ln_w[i] * lin_w[i];
            B += ln_b[i] * lin_w[i];
        }
        sW = W;
        sB = B + lin_b[0];
    }
    __syncthreads();

    double Ntot = (double)N_NODES * HID;
    double mu_d  = g_sum / Ntot;
    double var_d = g_sq / Ntot - mu_d * mu_d;
    float mu  = (float)mu_d;
    float inv = rsqrtf((float)var_d + LN_EPS);

    float cnt = fmaxf((float)g_cnt[t], 1.f);
    float y = inv * ((float)g_S[t] / cnt - mu * sW) + sB;
    out[t] = 1.f / (1.f + __expf(-y));
}

extern "C" void kernel_launch(void* const* d_in, const int* in_sizes, int n_in,
                              void* d_out, int out_size) {
    const float* x         = (const float*)d_in[0];
    const int*   ei        = (const int*)  d_in[1];
    const int*   batch     = (const int*)  d_in[2];
    const float* W_l       = (const float*)d_in[3];
    const float* b_l       = (const float*)d_in[4];
    const float* W_r       = (const float*)d_in[5];
    const float* b_r       = (const float*)d_in[6];
    const float* att       = (const float*)d_in[7];
    const float* conv_bias = (const float*)d_in[8];
    const float* ln_w      = (const float*)d_in[9];
    const float* ln_b      = (const float*)d_in[10];
    const float* lin_w     = (const float*)d_in[11];
    const float* lin_b     = (const float*)d_in[12];
    float* out = (float*)d_out;

    k_zero<<<256, 256>>>();
    k_hist<<<N_EDGES / 256, 256>>>(ei);
    k_scan1<<<SCAN_BLOCKS, 256>>>();
    k_scan2<<<1, 512>>>();
    k_scan3<<<SCAN_BLOCKS, 256>>>();
    k_scatter<<<N_EDGES / 256, 256>>>(ei);
    k_gat<<<GAT_BLOCKS, 256>>>(x, W_l, b_l, W_r, b_r, att, conv_bias, ln_w, lin_w, batch);
    k_final<<<1, N_GRAPHS>>>(ln_w, ln_b, lin_w, lin_b, out);
}